// round 13
// baseline (speedup 1.0000x reference)
#include <cuda_runtime.h>
#include <math.h>

#define NSEQ 256
#define CDIM 128
#define NHEAD 4
#define DHEAD 32
#define NROWS (NSEQ * NSEQ)

// ---------------- scratch (device globals; no allocation allowed) ----------------
__device__ float g_qkv[(size_t)NROWS * 3 * CDIM];   // 96 MB
__device__ float g_attn[(size_t)NROWS * CDIM];      // 32 MB
__device__ float g_sums[NSEQ * CDIM];               // row/col prefix sums
__device__ float g_h1[NSEQ * 2 * CDIM];
__device__ float g_h2[NSEQ * CDIM];
__device__ float g_bias_row[NSEQ * NSEQ];           // dscale*dist with mask folded
__device__ float g_bias_col[NSEQ * NSEQ];

// ---------------- helpers ----------------
__device__ __forceinline__ float warp_sum(float v) {
#pragma unroll
    for (int o = 16; o; o >>= 1) v += __shfl_xor_sync(0xffffffffu, v, o);
    return v;
}
__device__ __forceinline__ float warp_max(float v) {
#pragma unroll
    for (int o = 16; o; o >>= 1) v = fmaxf(v, __shfl_xor_sync(0xffffffffu, v, o));
    return v;
}
__device__ __forceinline__ float half16_sum(float v) {
#pragma unroll
    for (int o = 8; o; o >>= 1) v += __shfl_xor_sync(0xffffffffu, v, o);
    return v;
}
__device__ __forceinline__ unsigned f2tf32(float f) {
    unsigned u;
    asm("cvt.rna.tf32.f32 %0, %1;" : "=r"(u) : "f"(f));
    return u;
}
__device__ __forceinline__ void mma_tf32(float d[4], const unsigned a[4], const unsigned b[2]) {
    asm volatile(
        "mma.sync.aligned.m16n8k8.row.col.f32.tf32.tf32.f32 "
        "{%0,%1,%2,%3}, {%4,%5,%6,%7}, {%8,%9}, {%0,%1,%2,%3};"
        : "+f"(d[0]), "+f"(d[1]), "+f"(d[2]), "+f"(d[3])
        : "r"(a[0]), "r"(a[1]), "r"(a[2]), "r"(a[3]), "r"(b[0]), "r"(b[1]));
}

#define AS_STR 20
#define BS_STR 136

// ---------------- mask detect + fused bias tables ----------------
__global__ void maskbias_kernel(const unsigned char* __restrict__ m,
                                const float* __restrict__ dist,
                                const float* __restrict__ rdsc,
                                const float* __restrict__ cdsc) {
    __shared__ int flag;
    int tid = threadIdx.x;
    if (tid == 0) flag = 0;
    __syncthreads();
    int local = 0;
    for (int idx = tid; idx < NSEQ * NSEQ; idx += blockDim.x)
        if ((idx & 3) && m[idx]) local = 1;
    if (local) atomicOr(&flag, 1);
    __syncthreads();
    int isBytes = flag;
    float rs = rdsc[0], cs = cdsc[0];
    for (int idx = tid; idx < NSEQ * NSEQ; idx += blockDim.x) {
        int t = (idx & 255) * 256 + (idx >> 8);
        unsigned char mb = isBytes ? m[idx] : m[4 * (size_t)idx];
        unsigned char mt = isBytes ? m[t] : m[4 * (size_t)t];
        float dv = dist[idx];
        g_bias_row[idx] = mb ? -1e30f : rs * dv;
        g_bias_col[idx] = mt ? -1e30f : cs * dv;
    }
}

// ---------------- prefix sums ----------------
__global__ void rowsum_kernel(const float* __restrict__ pair) {
    int i = blockIdx.x, c = threadIdx.x;
    const float* p = pair + (size_t)i * NSEQ * CDIM + c;
    float s = 0.f;
#pragma unroll 4
    for (int k = 0; k < i; k++) s += __ldg(&p[(size_t)k * CDIM]);
    g_sums[i * CDIM + c] = s;
}

__global__ void colsum_kernel(const float* __restrict__ pr) {
    int j = blockIdx.x, c = threadIdx.x;
    const float* p = pr + (size_t)j * CDIM + c;
    float s = 0.f;
#pragma unroll 4
    for (int k = 0; k < j; k++) s += __ldg(&p[(size_t)k * NSEQ * CDIM]);
    g_sums[j * CDIM + c] = s;
}

// ---------------- fused tri-update + LayerNorm (warp per (i,j) row) ----------------
__global__ __launch_bounds__(256)
void trimix_ln_kernel(float* __restrict__ out, const float* __restrict__ src,
                      const float* __restrict__ single,
                      const float* __restrict__ g, const float* __restrict__ b,
                      int mode) {
    int lane = threadIdx.x & 31, warp = threadIdx.x >> 5;
    int row = blockIdx.x * 8 + warp;
    int i = row >> 8, j = row & 255;
    const float* sA = single + (size_t)(mode == 0 ? j : i) * CDIM;
    const float* sB = g_sums + (size_t)(mode == 0 ? i : j) * CDIM;
    const float* xr = src + (size_t)row * CDIM;

    float v[4];
    float mean = 0.f;
#pragma unroll
    for (int q = 0; q < 4; q++) {
        int c = q * 32 + lane;
        v[q] = xr[c] + sA[c] + sB[c];
        mean += v[q];
    }
    mean = warp_sum(mean) * (1.0f / CDIM);
    float var = 0.f;
#pragma unroll
    for (int q = 0; q < 4; q++) { float d = v[q] - mean; var += d * d; }
    var = warp_sum(var) * (1.0f / CDIM);
    float inv = rsqrtf(var + 1e-5f);
    float* orow = out + (size_t)row * CDIM;
#pragma unroll
    for (int q = 0; q < 4; q++) {
        int c = q * 32 + lane;
        orow[c] = (v[q] - mean) * inv * g[c] + b[c];
    }
}

__global__ __launch_bounds__(256)
void residual_ln_kernel(float* __restrict__ out, const float* __restrict__ x,
                        const float* __restrict__ y,
                        const float* __restrict__ g, const float* __restrict__ b,
                        int nrows) {
    int lane = threadIdx.x & 31, warp = threadIdx.x >> 5;
    int row = blockIdx.x * 8 + warp;
    if (row >= nrows) return;
    const float* xr = x + (size_t)row * CDIM;
    const float* yr = y + (size_t)row * CDIM;
    float v[4];
    float mean = 0.f;
#pragma unroll
    for (int q = 0; q < 4; q++) {
        int c = q * 32 + lane;
        v[q] = xr[c] + yr[c];
        mean += v[q];
    }
    mean = warp_sum(mean) * (1.0f / CDIM);
    float var = 0.f;
#pragma unroll
    for (int q = 0; q < 4; q++) { float d = v[q] - mean; var += d * d; }
    var = warp_sum(var) * (1.0f / CDIM);
    float inv = rsqrtf(var + 1e-5f);
    float* orow = out + (size_t)row * CDIM;
#pragma unroll
    for (int q = 0; q < 4; q++) {
        int c = q * 32 + lane;
        orow[c] = (v[q] - mean) * inv * g[c] + b[c];
    }
}

// ---------------- TF32 tensor-core GEMM 128x128, double-buffered BK=16 (validated R11) ----------------
__global__ __launch_bounds__(256)
void gemm_tf32_kernel(const float* __restrict__ A, const float* __restrict__ B,
                      const float* __restrict__ bias, float* __restrict__ C,
                      int M, int N, int K, int relu) {
    __shared__ unsigned As[2][128 * AS_STR];
    __shared__ unsigned Bs[2][16 * BS_STR];
    int tid = threadIdx.x;
    int wid = tid >> 5, lane = tid & 31;
    int g = lane >> 2, t = lane & 3;
    int wm = (wid & 3) * 32, wn = (wid >> 2) * 64;
    int m0 = blockIdx.y * 128, n0 = blockIdx.x * 128;
    int arow = tid >> 1, acolg = (tid & 1) << 3;
    int brow = tid >> 4, bcol = (tid & 15) << 3;
    const float* Ap = A + (size_t)(m0 + arow) * K;

    float acc[2][8][4] = {};

    {
        float4 a0 = *(const float4*)&Ap[acolg];
        float4 a1 = *(const float4*)&Ap[acolg + 4];
        unsigned* d = &As[0][arow * AS_STR + acolg];
        d[0] = f2tf32(a0.x); d[1] = f2tf32(a0.y); d[2] = f2tf32(a0.z); d[3] = f2tf32(a0.w);
        d[4] = f2tf32(a1.x); d[5] = f2tf32(a1.y); d[6] = f2tf32(a1.z); d[7] = f2tf32(a1.w);
        float4 b0 = *(const float4*)&B[(size_t)brow * N + n0 + bcol];
        float4 b1 = *(const float4*)&B[(size_t)brow * N + n0 + bcol + 4];
        unsigned* e = &Bs[0][brow * BS_STR + bcol];
        e[0] = f2tf32(b0.x); e[1] = f2tf32(b0.y); e[2] = f2tf32(b0.z); e[3] = f2tf32(b0.w);
        e[4] = f2tf32(b1.x); e[5] = f2tf32(b1.y); e[6] = f2tf32(b1.z); e[7] = f2tf32(b1.w);
    }
    __syncthreads();

    int buf = 0;
    for (int k0 = 16; k0 < K; k0 += 16) {
        float4 pa0 = *(const float4*)&Ap[k0 + acolg];
        float4 pa1 = *(const float4*)&Ap[k0 + acolg + 4];
        float4 pb0 = *(const float4*)&B[(size_t)(k0 + brow) * N + n0 + bcol];
        float4 pb1 = *(const float4*)&B[(size_t)(k0 + brow) * N + n0 + bcol + 4];
#pragma unroll
        for (int ks = 0; ks < 16; ks += 8) {
            unsigned af[2][4];
#pragma unroll
            for (int mt = 0; mt < 2; mt++) {
                int mb = wm + mt * 16;
                af[mt][0] = As[buf][(mb + g) * AS_STR + ks + t];
                af[mt][1] = As[buf][(mb + g + 8) * AS_STR + ks + t];
                af[mt][2] = As[buf][(mb + g) * AS_STR + ks + t + 4];
                af[mt][3] = As[buf][(mb + g + 8) * AS_STR + ks + t + 4];
            }
#pragma unroll
            for (int nt = 0; nt < 8; nt++) {
                unsigned bf[2];
                bf[0] = Bs[buf][(ks + t) * BS_STR + wn + nt * 8 + g];
                bf[1] = Bs[buf][(ks + t + 4) * BS_STR + wn + nt * 8 + g];
                mma_tf32(acc[0][nt], af[0], bf);
                mma_tf32(acc[1][nt], af[1], bf);
            }
        }
        int nb = buf ^ 1;
        unsigned* d = &As[nb][arow * AS_STR + acolg];
        d[0] = f2tf32(pa0.x); d[1] = f2tf32(pa0.y); d[2] = f2tf32(pa0.z); d[3] = f2tf32(pa0.w);
        d[4] = f2tf32(pa1.x); d[5] = f2tf32(pa1.y); d[6] = f2tf32(pa1.z); d[7] = f2tf32(pa1.w);
        unsigned* e = &Bs[nb][brow * BS_STR + bcol];
        e[0] = f2tf32(pb0.x); e[1] = f2tf32(pb0.y); e[2] = f2tf32(pb0.z); e[3] = f2tf32(pb0.w);
        e[4] = f2tf32(pb1.x); e[5] = f2tf32(pb1.y); e[6] = f2tf32(pb1.z); e[7] = f2tf32(pb1.w);
        __syncthreads();
        buf = nb;
    }
#pragma unroll
    for (int ks = 0; ks < 16; ks += 8) {
        unsigned af[2][4];
#pragma unroll
        for (int mt = 0; mt < 2; mt++) {
            int mb = wm + mt * 16;
            af[mt][0] = As[buf][(mb + g) * AS_STR + ks + t];
            af[mt][1] = As[buf][(mb + g + 8) * AS_STR + ks + t];
            af[mt][2] = As[buf][(mb + g) * AS_STR + ks + t + 4];
            af[mt][3] = As[buf][(mb + g + 8) * AS_STR + ks + t + 4];
        }
#pragma unroll
        for (int nt = 0; nt < 8; nt++) {
            unsigned bf[2];
            bf[0] = Bs[buf][(ks + t) * BS_STR + wn + nt * 8 + g];
            bf[1] = Bs[buf][(ks + t + 4) * BS_STR + wn + nt * 8 + g];
            mma_tf32(acc[0][nt], af[0], bf);
            mma_tf32(acc[1][nt], af[1], bf);
        }
    }

#pragma unroll
    for (int nt = 0; nt < 8; nt++) {
        int cb = n0 + wn + nt * 8 + 2 * t;
        float b0 = __ldg(&bias[cb]), b1 = __ldg(&bias[cb + 1]);
#pragma unroll
        for (int mt = 0; mt < 2; mt++) {
            int r = m0 + wm + mt * 16 + g;
            float2 lo = make_float2(acc[mt][nt][0] + b0, acc[mt][nt][1] + b1);
            float2 hi = make_float2(acc[mt][nt][2] + b0, acc[mt][nt][3] + b1);
            if (relu) {
                lo.x = fmaxf(lo.x, 0.f); lo.y = fmaxf(lo.y, 0.f);
                hi.x = fmaxf(hi.x, 0.f); hi.y = fmaxf(hi.y, 0.f);
            }
            *(float2*)&C[(size_t)r * N + cb] = lo;
            *(float2*)&C[(size_t)(r + 8) * N + cb] = hi;
        }
    }
}

// ---------------- FMA SGEMM 128x128x16 (validated; used for MLP) ----------------
__global__ __launch_bounds__(256)
void gemm128_kernel(const float* __restrict__ A, const float* __restrict__ B,
                    const float* __restrict__ bias, float* __restrict__ C,
                    int M, int N, int K, int relu) {
    __shared__ float As[2][16][128];
    __shared__ float Bs[2][16][132];
    int tid = threadIdx.x;
    int m0 = blockIdx.y * 128, n0 = blockIdx.x * 128;
    int tx = tid & 15, ty = tid >> 4;
    int arow = tid >> 1, acolg = (tid & 1) << 3;
    int brow = tid >> 5, bcol = (tid & 31) << 2;
    const float* Aptr = A + (size_t)(m0 + arow) * K;

    {
        float4 a0 = *(const float4*)&Aptr[acolg];
        float4 a1 = *(const float4*)&Aptr[acolg + 4];
        As[0][acolg + 0][arow] = a0.x; As[0][acolg + 1][arow] = a0.y;
        As[0][acolg + 2][arow] = a0.z; As[0][acolg + 3][arow] = a0.w;
        As[0][acolg + 4][arow] = a1.x; As[0][acolg + 5][arow] = a1.y;
        As[0][acolg + 6][arow] = a1.z; As[0][acolg + 7][arow] = a1.w;
        *(float4*)&Bs[0][brow][bcol]     = *(const float4*)&B[(size_t)brow * N + n0 + bcol];
        *(float4*)&Bs[0][brow + 8][bcol] = *(const float4*)&B[(size_t)(brow + 8) * N + n0 + bcol];
    }
    __syncthreads();

    float acc[8][8] = {};
    int buf = 0;
    for (int k0 = 16; k0 < K; k0 += 16) {
        float4 na0 = *(const float4*)&Aptr[k0 + acolg];
        float4 na1 = *(const float4*)&Aptr[k0 + acolg + 4];
        float4 nb0 = *(const float4*)&B[(size_t)(k0 + brow) * N + n0 + bcol];
        float4 nb1 = *(const float4*)&B[(size_t)(k0 + brow + 8) * N + n0 + bcol];
#pragma unroll
        for (int kk = 0; kk < 16; kk++) {
            float a[8], b[8];
            *(float4*)(a)     = *(const float4*)&As[buf][kk][ty * 8];
            *(float4*)(a + 4) = *(const float4*)&As[buf][kk][ty * 8 + 4];
            *(float4*)(b)     = *(const float4*)&Bs[buf][kk][tx * 8];
            *(float4*)(b + 4) = *(const float4*)&Bs[buf][kk][tx * 8 + 4];
#pragma unroll
            for (int i2 = 0; i2 < 8; i2++)
#pragma unroll
                for (int j2 = 0; j2 < 8; j2++)
                    acc[i2][j2] += a[i2] * b[j2];
        }
        int nb = buf ^ 1;
        As[nb][acolg + 0][arow] = na0.x; As[nb][acolg + 1][arow] = na0.y;
        As[nb][acolg + 2][arow] = na0.z; As[nb][acolg + 3][arow] = na0.w;
        As[nb][acolg + 4][arow] = na1.x; As[nb][acolg + 5][arow] = na1.y;
        As[nb][acolg + 6][arow] = na1.z; As[nb][acolg + 7][arow] = na1.w;
        *(float4*)&Bs[nb][brow][bcol]     = nb0;
        *(float4*)&Bs[nb][brow + 8][bcol] = nb1;
        __syncthreads();
        buf = nb;
    }
#pragma unroll
    for (int kk = 0; kk < 16; kk++) {
        float a[8], b[8];
        *(float4*)(a)     = *(const float4*)&As[buf][kk][ty * 8];
        *(float4*)(a + 4) = *(const float4*)&As[buf][kk][ty * 8 + 4];
        *(float4*)(b)     = *(const float4*)&Bs[buf][kk][tx * 8];
        *(float4*)(b + 4) = *(const float4*)&Bs[buf][kk][tx * 8 + 4];
#pragma unroll
        for (int i2 = 0; i2 < 8; i2++)
#pragma unroll
            for (int j2 = 0; j2 < 8; j2++)
                acc[i2][j2] += a[i2] * b[j2];
    }

    float4 bi0 = *(const float4*)&bias[n0 + tx * 8];
    float4 bi1 = *(const float4*)&bias[n0 + tx * 8 + 4];
#pragma unroll
    for (int r = 0; r < 8; r++) {
        float* crow = C + (size_t)(m0 + ty * 8 + r) * N + n0 + tx * 8;
        float4 o0 = make_float4(acc[r][0] + bi0.x, acc[r][1] + bi0.y,
                                acc[r][2] + bi0.z, acc[r][3] + bi0.w);
        float4 o1 = make_float4(acc[r][4] + bi1.x, acc[r][5] + bi1.y,
                                acc[r][6] + bi1.z, acc[r][7] + bi1.w);
        if (relu) {
            o0.x = fmaxf(o0.x, 0.f); o0.y = fmaxf(o0.y, 0.f);
            o0.z = fmaxf(o0.z, 0.f); o0.w = fmaxf(o0.w, 0.f);
            o1.x = fmaxf(o1.x, 0.f); o1.y = fmaxf(o1.y, 0.f);
            o1.z = fmaxf(o1.w, 0.f); o1.w = fmaxf(o1.w, 0.f);
        }
        if (relu) { o1.z = fmaxf(acc[r][6] + bi1.z, 0.f); }  // keep exact semantics
        *(float4*)crow = o0;
        *(float4*)(crow + 4) = o1;
    }
}

// ---------------- FMA out-proj + residual + LayerNorm (validated R6-R12) ----------------
__global__ __launch_bounds__(256)
void gemm_wo_ln_kernel(const float* __restrict__ A, const float* __restrict__ B,
                       const float* __restrict__ bias, const float* __restrict__ xres,
                       const float* __restrict__ g, const float* __restrict__ bb,
                       float* __restrict__ out) {
    __shared__ float As[2][16][128];
    __shared__ float Bs[2][16][132];
    int tid = threadIdx.x;
    int m0 = blockIdx.x * 128;
    int tx = tid & 15, ty = tid >> 4;
    int arow = tid >> 1, acolg = (tid & 1) << 3;
    int brow = tid >> 5, bcol = (tid & 31) << 2;
    const float* Aptr = A + (size_t)(m0 + arow) * 128;

    {
        float4 a0 = *(const float4*)&Aptr[acolg];
        float4 a1 = *(const float4*)&Aptr[acolg + 4];
        As[0][acolg + 0][arow] = a0.x; As[0][acolg + 1][arow] = a0.y;
        As[0][acolg + 2][arow] = a0.z; As[0][acolg + 3][arow] = a0.w;
        As[0][acolg + 4][arow] = a1.x; As[0][acolg + 5][arow] = a1.y;
        As[0][acolg + 6][arow] = a1.z; As[0][acolg + 7][arow] = a1.w;
        *(float4*)&Bs[0][brow][bcol]     = *(const float4*)&B[(size_t)brow * 128 + bcol];
        *(float4*)&Bs[0][brow + 8][bcol] = *(const float4*)&B[(size_t)(brow + 8) * 128 + bcol];
    }
    __syncthreads();

    float acc[8][8] = {};
    int buf = 0;
    for (int k0 = 16; k0 < 128; k0 += 16) {
        float4 na0 = *(const float4*)&Aptr[k0 + acolg];
        float4 na1 = *(const float4*)&Aptr[k0 + acolg + 4];
        float4 nb0 = *(const float4*)&B[(size_t)(k0 + brow) * 128 + bcol];
        float4 nb1 = *(const float4*)&B[(size_t)(k0 + brow + 8) * 128 + bcol];
#pragma unroll
        for (int kk = 0; kk < 16; kk++) {
            float a[8], b[8];
            *(float4*)(a)     = *(const float4*)&As[buf][kk][ty * 8];
            *(float4*)(a + 4) = *(const float4*)&As[buf][kk][ty * 8 + 4];
            *(float4*)(b)     = *(const float4*)&Bs[buf][kk][tx * 8];
            *(float4*)(b + 4) = *(const float4*)&Bs[buf][kk][tx * 8 + 4];
#pragma unroll
            for (int i2 = 0; i2 < 8; i2++)
#pragma unroll
                for (int j2 = 0; j2 < 8; j2++)
                    acc[i2][j2] += a[i2] * b[j2];
        }
        int nb = buf ^ 1;
        As[nb][acolg + 0][arow] = na0.x; As[nb][acolg + 1][arow] = na0.y;
        As[nb][acolg + 2][arow] = na0.z; As[nb][acolg + 3][arow] = na0.w;
        As[nb][acolg + 4][arow] = na1.x; As[nb][acolg + 5][arow] = na1.y;
        As[nb][acolg + 6][arow] = na1.z; As[nb][acolg + 7][arow] = na1.w;
        *(float4*)&Bs[nb][brow][bcol]     = nb0;
        *(float4*)&Bs[nb][brow + 8][bcol] = nb1;
        __syncthreads();
        buf = nb;
    }
#pragma unroll
    for (int kk = 0; kk < 16; kk++) {
        float a[8], b[8];
        *(float4*)(a)     = *(const float4*)&As[buf][kk][ty * 8];
        *(float4*)(a + 4) = *(const float4*)&As[buf][kk][ty * 8 + 4];
        *(float4*)(b)     = *(const float4*)&Bs[buf][kk][tx * 8];
        *(float4*)(b + 4) = *(const float4*)&Bs[buf][kk][tx * 8 + 4];
#pragma unroll
        for (int i2 = 0; i2 < 8; i2++)
#pragma unroll
            for (int j2 = 0; j2 < 8; j2++)
                acc[i2][j2] += a[i2] * b[j2];
    }

    float4 bi0 = *(const float4*)&bias[tx * 8];
    float4 bi1 = *(const float4*)&bias[tx * 8 + 4];
    float4 g0  = *(const float4*)&g[tx * 8];
    float4 g1  = *(const float4*)&g[tx * 8 + 4];
    float4 be0 = *(const float4*)&bb[tx * 8];
    float4 be1 = *(const float4*)&bb[tx * 8 + 4];
#pragma unroll
    for (int r = 0; r < 8; r++) {
        int row = m0 + ty * 8 + r;
        const float* xr = xres + (size_t)row * 128 + tx * 8;
        float4 x0 = *(const float4*)xr;
        float4 x1 = *(const float4*)(xr + 4);
        float v[8];
        v[0] = acc[r][0] + bi0.x + x0.x; v[1] = acc[r][1] + bi0.y + x0.y;
        v[2] = acc[r][2] + bi0.z + x0.z; v[3] = acc[r][3] + bi0.w + x0.w;
        v[4] = acc[r][4] + bi1.x + x1.x; v[5] = acc[r][5] + bi1.y + x1.y;
        v[6] = acc[r][6] + bi1.z + x1.z; v[7] = acc[r][7] + bi1.w + x1.w;
        float s = 0.f;
#pragma unroll
        for (int q = 0; q < 8; q++) s += v[q];
        s = half16_sum(s);
        float mean = s * (1.0f / 128.0f);
        float d2 = 0.f;
#pragma unroll
        for (int q = 0; q < 8; q++) { float d = v[q] - mean; d2 += d * d; }
        d2 = half16_sum(d2);
        float inv = rsqrtf(d2 * (1.0f / 128.0f) + 1e-5f);
        float* orow = out + (size_t)row * 128 + tx * 8;
        float4 o0, o1;
        o0.x = (v[0] - mean) * inv * g0.x + be0.x;
        o0.y = (v[1] - mean) * inv * g0.y + be0.y;
        o0.z = (v[2] - mean) * inv * g0.z + be0.z;
        o0.w = (v[3] - mean) * inv * g0.w + be0.w;
        o1.x = (v[4] - mean) * inv * g1.x + be1.x;
        o1.y = (v[5] - mean) * inv * g1.y + be1.y;
        o1.z = (v[6] - mean) * inv * g1.z + be1.z;
        o1.w = (v[7] - mean) * inv * g1.w + be1.w;
        *(float4*)orow = o0;
        *(float4*)(orow + 4) = o1;
    }
}

// ---------------- attention: 512 threads, 16 warps, column-split halves ----------------
// warp (wr = w&7, wc = w>>3): rows wr*8..+7, cols [wc*128, wc*128+128)
// smem: Qs[32][68] | Ks[32][260] | Vs[256][33] | S[64][256] | redM[2][64] | redS[2][64] | OT[64][33]
#define ATT_QS 0
#define ATT_KS 2176
#define ATT_VS (ATT_KS + 32 * 260)
#define ATT_S  (ATT_VS + 256 * 33)
#define ATT_RM (ATT_S + 64 * 256)
#define ATT_RS (ATT_RM + 128)
#define ATT_OT (ATT_RS + 128)
#define ATT_FLOATS (ATT_OT + 64 * 33)
#define ATT_SMEM_BYTES (ATT_FLOATS * 4)

__global__ __launch_bounds__(512)
void attn_tile_kernel(const float* __restrict__ qkv, const float* __restrict__ biasmat,
                      float* __restrict__ out) {
    extern __shared__ float sh[];
    float* Qs   = sh + ATT_QS;   // Q^T [d][j]
    float* Ks   = sh + ATT_KS;   // K^T [d][k] stride 260
    float* Vs   = sh + ATT_VS;   // V  [k][d] stride 33
    float* S    = sh + ATT_S;    // exp-weights [j][k]
    float* redM = sh + ATT_RM;   // [2][64] partial row max
    float* redS = sh + ATT_RS;   // [2][64] partial row sum
    float* OT   = sh + ATT_OT;   // [64][33] partial AV from half 0
    int jt = blockIdx.x, h = blockIdx.y, i = blockIdx.z;
    int tid = threadIdx.x, lane = tid & 31, w = tid >> 5;
    int wr = w & 7, wc = w >> 3;
    const float* base = qkv + (size_t)i * NSEQ * 384;

    for (int idx = tid; idx < 64 * 32; idx += 512) {
        int j = idx >> 5, d = idx & 31;
        Qs[d * 68 + j] = base[(size_t)(jt * 64 + j) * 384 + h * 32 + d];
    }
    for (int idx = tid; idx < 256 * 32; idx += 512) {
        int k = idx >> 5, d = idx & 31;
        Ks[d * 260 + k] = base[(size_t)k * 384 + 128 + h * 32 + d];
        Vs[k * 33 + d]  = base[(size_t)k * 384 + 256 + h * 32 + d];
    }
    __syncthreads();

    const float scale = 0.17677669529663687f;  // 1/sqrt(32)
    int colbase = wc * 128 + lane * 4;

    // ---- QK^T: warp covers rows wr*8..+7 x its 128-col half; thread 4 cols ----
    float acc[8][4];
#pragma unroll
    for (int r = 0; r < 8; r++)
#pragma unroll
        for (int c = 0; c < 4; c++) acc[r][c] = 0.f;

#pragma unroll 4
    for (int d = 0; d < 32; d++) {
        float qr[8], kr[4];
        *(float4*)(qr)     = *(const float4*)&Qs[d * 68 + wr * 8];       // broadcast
        *(float4*)(qr + 4) = *(const float4*)&Qs[d * 68 + wr * 8 + 4];   // broadcast
        *(float4*)(kr)     = *(const float4*)&Ks[d * 260 + colbase];     // conflict-free
#pragma unroll
        for (int r = 0; r < 8; r++)
#pragma unroll
            for (int c = 0; c < 4; c++)
                acc[r][c] += qr[r] * kr[c];
    }

    // ---- bias + partial row max ----
    int jrow0 = jt * 64 + wr * 8;
    float v[8][4];
    float pmax[8];
#pragma unroll
    for (int r = 0; r < 8; r++) {
        float4 b0 = __ldg((const float4*)(biasmat + (size_t)(jrow0 + r) * 256 + colbase));
        v[r][0] = fmaf(acc[r][0], scale, b0.x);
        v[r][1] = fmaf(acc[r][1], scale, b0.y);
        v[r][2] = fmaf(acc[r][2], scale, b0.z);
        v[r][3] = fmaf(acc[r][3], scale, b0.w);
        float mx = fmaxf(fmaxf(v[r][0], v[r][1]), fmaxf(v[r][2], v[r][3]));
        pmax[r] = warp_max(mx);
    }
    if (lane == 0) {
#pragma unroll
        for (int r = 0; r < 8; r++) redM[wc * 64 + wr * 8 + r] = pmax[r];
    }
    __syncthreads();

    // ---- global max, exp, partial sum; write S (own half) ----
    float psum[8];
#pragma unroll
    for (int r = 0; r < 8; r++) {
        float gmax = fmaxf(pmax[r], redM[(1 - wc) * 64 + wr * 8 + r]);
        v[r][0] = __expf(v[r][0] - gmax);
        v[r][1] = __expf(v[r][1] - gmax);
        v[r][2] = __expf(v[r][2] - gmax);
        v[r][3] = __expf(v[r][3] - gmax);
        float s = v[r][0] + v[r][1] + v[r][2] + v[r][3];
        psum[r] = warp_sum(s);
        *(float4*)&S[(wr * 8 + r) * 256 + colbase] = *(float4*)v[r];
    }
    if (lane == 0) {
#pragma unroll
        for (int r = 0; r < 8; r++) redS[wc * 64 + wr * 8 + r] = psum[r];
    }
    __syncthreads();

    float invs[8];
#pragma unroll
    for (int r = 0; r < 8; r++)
        invs[r] = 1.0f / (psum[r] + redS[(1 - wc) * 64 + wr * 8 + r]);

    // ---- AV over own k-half: rows wr*8..+7, d = lane ----
    float o[8] = {};
    int kbase = wc * 128;
    for (int k0 = 0; k0 < 128; k0 += 4) {
        int kk = kbase + k0;
        float v0 = Vs[(kk + 0) * 33 + lane];
        float v1 = Vs[(kk + 1) * 33 + lane];
        float v2 = Vs[(kk + 2) * 33 + lane];
        float v3 = Vs[(kk + 3) * 33 + lane];
#pragma unroll
        for (int r = 0; r < 8; r++) {
            float4 wv = *(const float4*)&S[(wr * 8 + r) * 256 + kk];  // broadcast
            o[r] += wv.x * v0 + wv.y * v1 + wv.z * v2 + wv.w * v3;
        }
    }

    // ---- combine halves: wc=0 stages partials, wc=1 adds + writes ----
    if (wc == 0) {
#pragma unroll
        for (int r = 0; r < 8; r++) OT[(wr * 8 + r) * 33 + lane] = o[r];
    }
    __syncthreads();
    if (wc == 1) {
#pragma unroll
        for (int r = 0; r < 8; r++) {
            float tot = o[r] + OT[(wr * 8 + r) * 33 + lane];
            out[((size_t)i * NSEQ + jrow0 + r) * CDIM + h * 32 + lane] = tot * invs[r];
        }
    }
}

// ---------------- launch ----------------
extern "C" void kernel_launch(void* const* d_in, const int* in_sizes, int n_in,
                              void* d_out, int out_size) {
    const float* pair      = (const float*)d_in[0];
    const float* single    = (const float*)d_in[1];
    const unsigned char* mask = (const unsigned char*)d_in[2];
    const float* dist      = (const float*)d_in[3];
    const float* row_Wqkv  = (const float*)d_in[4];
    const float* row_bqkv  = (const float*)d_in[5];
    const float* row_Wo    = (const float*)d_in[6];
    const float* row_bo    = (const float*)d_in[7];
    const float* row_dsc   = (const float*)d_in[8];
    const float* col_Wqkv  = (const float*)d_in[9];
    const float* col_bqkv  = (const float*)d_in[10];
    const float* col_Wo    = (const float*)d_in[11];
    const float* col_bo    = (const float*)d_in[12];
    const float* col_dsc   = (const float*)d_in[13];
    const float* pnr_g     = (const float*)d_in[14];
    const float* pnr_b     = (const float*)d_in[15];
    const float* pnc_g     = (const float*)d_in[16];
    const float* pnc_b     = (const float*)d_in[17];
    const float* sn_g      = (const float*)d_in[18];
    const float* sn_b      = (const float*)d_in[19];
    const float* W1        = (const float*)d_in[20];
    const float* b1        = (const float*)d_in[21];
    const float* W2        = (const float*)d_in[22];
    const float* b2        = (const float*)d_in[23];

    float* pr = (float*)d_out;                               // [256,256,128]
    float* sr = pr + (size_t)NROWS * CDIM;                   // [256,128]

    float *qkv_p, *attn_p, *h1_p, *h2_p, *brow_p, *bcol_p;
    cudaGetSymbolAddress((void**)&qkv_p, g_qkv);
    cudaGetSymbolAddress((void**)&attn_p, g_attn);
    cudaGetSymbolAddress((void**)&h1_p, g_h1);
    cudaGetSymbolAddress((void**)&h2_p, g_h2);
    cudaGetSymbolAddress((void**)&brow_p, g_bias_row);
    cudaGetSymbolAddress((void**)&bcol_p, g_bias_col);

    cudaFuncSetAttribute(attn_tile_kernel, cudaFuncAttributeMaxDynamicSharedMemorySize,
                         ATT_SMEM_BYTES);

    // mask detection + fused bias tables
    maskbias_kernel<<<1, 1024>>>(mask, dist, row_dsc, col_dsc);

    // ---- stage 1: pr = LN(pair + tri_update_out(pair, single)) ----
    rowsum_kernel<<<NSEQ, CDIM>>>(pair);
    trimix_ln_kernel<<<NROWS / 8, 256>>>(pr, pair, single, pnr_g, pnr_b, 0);

    // ---- stage 2: pr = LN(pr + row_attn(pr)) ----
    gemm_tf32_kernel<<<dim3(3, 512), 256>>>(pr, row_Wqkv, row_bqkv, qkv_p, NROWS, 384, 128, 0);
    attn_tile_kernel<<<dim3(4, NHEAD, NSEQ), 512, ATT_SMEM_BYTES>>>(qkv_p, brow_p, attn_p);
    gemm_wo_ln_kernel<<<512, 256>>>(attn_p, row_Wo, row_bo, pr, pnr_g, pnr_b, pr);

    // ---- stage 3: pr = LN(pr + tri_update_in(pr, single)) ----
    colsum_kernel<<<NSEQ, CDIM>>>(pr);
    trimix_ln_kernel<<<NROWS / 8, 256>>>(pr, pr, single, pnc_g, pnc_b, 1);

    // ---- stage 4: pr = LN(pr + col_attn(pr)) ----
    gemm_tf32_kernel<<<dim3(3, 512), 256>>>(pr, col_Wqkv, col_bqkv, qkv_p, NROWS, 384, 128, 0);
    attn_tile_kernel<<<dim3(4, NHEAD, NSEQ), 512, ATT_SMEM_BYTES>>>(qkv_p, bcol_p, attn_p);
    gemm_wo_ln_kernel<<<512, 256>>>(attn_p, col_Wo, col_bo, pr, pnc_g, pnc_b, pr);

    // ---- single-rep MLP + LN ----
    gemm128_kernel<<<dim3(2, 2), 256>>>(single, W1, b1, h1_p, NSEQ, 256, 128, 1);
    gemm128_kernel<<<dim3(1, 2), 256>>>(h1_p, W2, b2, h2_p, NSEQ, 128, 256, 1);
    residual_ln_kernel<<<NSEQ / 8, 256>>>(sr, single, h2_p, sn_g, sn_b, NSEQ);
}

// round 16
// speedup vs baseline: 1.2952x; 1.2952x over previous
#include <cuda_runtime.h>
#include <math.h>

#define NSEQ 256
#define CDIM 128
#define NHEAD 4
#define DHEAD 32
#define NROWS (NSEQ * NSEQ)

// ---------------- scratch (device globals; no allocation allowed) ----------------
__device__ float g_qkv[(size_t)NROWS * 3 * CDIM];   // 96 MB
__device__ float g_attn[(size_t)NROWS * CDIM];      // 32 MB
__device__ float g_sums[NSEQ * CDIM];               // row/col prefix sums
__device__ float g_h1[NSEQ * 2 * CDIM];
__device__ float g_h2[NSEQ * CDIM];
__device__ float g_bias_row[NSEQ * NSEQ];           // dscale*dist with mask folded
__device__ float g_bias_col[NSEQ * NSEQ];

// ---------------- helpers ----------------
__device__ __forceinline__ float warp_sum(float v) {
#pragma unroll
    for (int o = 16; o; o >>= 1) v += __shfl_xor_sync(0xffffffffu, v, o);
    return v;
}
__device__ __forceinline__ float warp_max(float v) {
#pragma unroll
    for (int o = 16; o; o >>= 1) v = fmaxf(v, __shfl_xor_sync(0xffffffffu, v, o));
    return v;
}
__device__ __forceinline__ float half16_sum(float v) {
#pragma unroll
    for (int o = 8; o; o >>= 1) v += __shfl_xor_sync(0xffffffffu, v, o);
    return v;
}
__device__ __forceinline__ unsigned f2tf32(float f) {
    unsigned u;
    asm("cvt.rna.tf32.f32 %0, %1;" : "=r"(u) : "f"(f));
    return u;
}
__device__ __forceinline__ void mma_tf32(float d[4], const unsigned a[4], const unsigned b[2]) {
    asm volatile(
        "mma.sync.aligned.m16n8k8.row.col.f32.tf32.tf32.f32 "
        "{%0,%1,%2,%3}, {%4,%5,%6,%7}, {%8,%9}, {%0,%1,%2,%3};"
        : "+f"(d[0]), "+f"(d[1]), "+f"(d[2]), "+f"(d[3])
        : "r"(a[0]), "r"(a[1]), "r"(a[2]), "r"(a[3]), "r"(b[0]), "r"(b[1]));
}

#define AS_STR 20
#define BS_STR 136

// ---------------- mask detect + fused bias tables ----------------
__global__ void maskbias_kernel(const unsigned char* __restrict__ m,
                                const float* __restrict__ dist,
                                const float* __restrict__ rdsc,
                                const float* __restrict__ cdsc) {
    __shared__ int flag;
    int tid = threadIdx.x;
    if (tid == 0) flag = 0;
    __syncthreads();
    int local = 0;
    for (int idx = tid; idx < NSEQ * NSEQ; idx += blockDim.x)
        if ((idx & 3) && m[idx]) local = 1;
    if (local) atomicOr(&flag, 1);
    __syncthreads();
    int isBytes = flag;
    float rs = rdsc[0], cs = cdsc[0];
    for (int idx = tid; idx < NSEQ * NSEQ; idx += blockDim.x) {
        int t = (idx & 255) * 256 + (idx >> 8);
        unsigned char mb = isBytes ? m[idx] : m[4 * (size_t)idx];
        unsigned char mt = isBytes ? m[t] : m[4 * (size_t)t];
        float dv = dist[idx];
        g_bias_row[idx] = mb ? -1e30f : rs * dv;
        g_bias_col[idx] = mt ? -1e30f : cs * dv;
    }
}

// ---------------- prefix sums ----------------
__global__ void rowsum_kernel(const float* __restrict__ pair) {
    int i = blockIdx.x, c = threadIdx.x;
    const float* p = pair + (size_t)i * NSEQ * CDIM + c;
    float s = 0.f;
#pragma unroll 4
    for (int k = 0; k < i; k++) s += __ldg(&p[(size_t)k * CDIM]);
    g_sums[i * CDIM + c] = s;
}

__global__ void colsum_kernel(const float* __restrict__ pr) {
    int j = blockIdx.x, c = threadIdx.x;
    const float* p = pr + (size_t)j * CDIM + c;
    float s = 0.f;
#pragma unroll 4
    for (int k = 0; k < j; k++) s += __ldg(&p[(size_t)k * NSEQ * CDIM]);
    g_sums[j * CDIM + c] = s;
}

// ---------------- fused tri-update + LayerNorm (warp per (i,j) row) ----------------
__global__ __launch_bounds__(256)
void trimix_ln_kernel(float* __restrict__ out, const float* __restrict__ src,
                      const float* __restrict__ single,
                      const float* __restrict__ g, const float* __restrict__ b,
                      int mode) {
    int lane = threadIdx.x & 31, warp = threadIdx.x >> 5;
    int row = blockIdx.x * 8 + warp;
    int i = row >> 8, j = row & 255;
    const float* sA = single + (size_t)(mode == 0 ? j : i) * CDIM;
    const float* sB = g_sums + (size_t)(mode == 0 ? i : j) * CDIM;
    const float* xr = src + (size_t)row * CDIM;

    float v[4];
    float mean = 0.f;
#pragma unroll
    for (int q = 0; q < 4; q++) {
        int c = q * 32 + lane;
        v[q] = xr[c] + sA[c] + sB[c];
        mean += v[q];
    }
    mean = warp_sum(mean) * (1.0f / CDIM);
    float var = 0.f;
#pragma unroll
    for (int q = 0; q < 4; q++) { float d = v[q] - mean; var += d * d; }
    var = warp_sum(var) * (1.0f / CDIM);
    float inv = rsqrtf(var + 1e-5f);
    float* orow = out + (size_t)row * CDIM;
#pragma unroll
    for (int q = 0; q < 4; q++) {
        int c = q * 32 + lane;
        orow[c] = (v[q] - mean) * inv * g[c] + b[c];
    }
}

__global__ __launch_bounds__(256)
void residual_ln_kernel(float* __restrict__ out, const float* __restrict__ x,
                        const float* __restrict__ y,
                        const float* __restrict__ g, const float* __restrict__ b,
                        int nrows) {
    int lane = threadIdx.x & 31, warp = threadIdx.x >> 5;
    int row = blockIdx.x * 8 + warp;
    if (row >= nrows) return;
    const float* xr = x + (size_t)row * CDIM;
    const float* yr = y + (size_t)row * CDIM;
    float v[4];
    float mean = 0.f;
#pragma unroll
    for (int q = 0; q < 4; q++) {
        int c = q * 32 + lane;
        v[q] = xr[c] + yr[c];
        mean += v[q];
    }
    mean = warp_sum(mean) * (1.0f / CDIM);
    float var = 0.f;
#pragma unroll
    for (int q = 0; q < 4; q++) { float d = v[q] - mean; var += d * d; }
    var = warp_sum(var) * (1.0f / CDIM);
    float inv = rsqrtf(var + 1e-5f);
    float* orow = out + (size_t)row * CDIM;
#pragma unroll
    for (int q = 0; q < 4; q++) {
        int c = q * 32 + lane;
        orow[c] = (v[q] - mean) * inv * g[c] + b[c];
    }
}

// ---------------- TF32 tensor-core GEMM 128x128, double-buffered BK=16 (validated R11/R12) ----------------
__global__ __launch_bounds__(256)
void gemm_tf32_kernel(const float* __restrict__ A, const float* __restrict__ B,
                      const float* __restrict__ bias, float* __restrict__ C,
                      int M, int N, int K, int relu) {
    __shared__ unsigned As[2][128 * AS_STR];
    __shared__ unsigned Bs[2][16 * BS_STR];
    int tid = threadIdx.x;
    int wid = tid >> 5, lane = tid & 31;
    int g = lane >> 2, t = lane & 3;
    int wm = (wid & 3) * 32, wn = (wid >> 2) * 64;
    int m0 = blockIdx.y * 128, n0 = blockIdx.x * 128;
    int arow = tid >> 1, acolg = (tid & 1) << 3;
    int brow = tid >> 4, bcol = (tid & 15) << 3;
    const float* Ap = A + (size_t)(m0 + arow) * K;

    float acc[2][8][4] = {};

    {
        float4 a0 = *(const float4*)&Ap[acolg];
        float4 a1 = *(const float4*)&Ap[acolg + 4];
        unsigned* d = &As[0][arow * AS_STR + acolg];
        d[0] = f2tf32(a0.x); d[1] = f2tf32(a0.y); d[2] = f2tf32(a0.z); d[3] = f2tf32(a0.w);
        d[4] = f2tf32(a1.x); d[5] = f2tf32(a1.y); d[6] = f2tf32(a1.z); d[7] = f2tf32(a1.w);
        float4 b0 = *(const float4*)&B[(size_t)brow * N + n0 + bcol];
        float4 b1 = *(const float4*)&B[(size_t)brow * N + n0 + bcol + 4];
        unsigned* e = &Bs[0][brow * BS_STR + bcol];
        e[0] = f2tf32(b0.x); e[1] = f2tf32(b0.y); e[2] = f2tf32(b0.z); e[3] = f2tf32(b0.w);
        e[4] = f2tf32(b1.x); e[5] = f2tf32(b1.y); e[6] = f2tf32(b1.z); e[7] = f2tf32(b1.w);
    }
    __syncthreads();

    int buf = 0;
    for (int k0 = 16; k0 < K; k0 += 16) {
        float4 pa0 = *(const float4*)&Ap[k0 + acolg];
        float4 pa1 = *(const float4*)&Ap[k0 + acolg + 4];
        float4 pb0 = *(const float4*)&B[(size_t)(k0 + brow) * N + n0 + bcol];
        float4 pb1 = *(const float4*)&B[(size_t)(k0 + brow) * N + n0 + bcol + 4];
#pragma unroll
        for (int ks = 0; ks < 16; ks += 8) {
            unsigned af[2][4];
#pragma unroll
            for (int mt = 0; mt < 2; mt++) {
                int mb = wm + mt * 16;
                af[mt][0] = As[buf][(mb + g) * AS_STR + ks + t];
                af[mt][1] = As[buf][(mb + g + 8) * AS_STR + ks + t];
                af[mt][2] = As[buf][(mb + g) * AS_STR + ks + t + 4];
                af[mt][3] = As[buf][(mb + g + 8) * AS_STR + ks + t + 4];
            }
#pragma unroll
            for (int nt = 0; nt < 8; nt++) {
                unsigned bf[2];
                bf[0] = Bs[buf][(ks + t) * BS_STR + wn + nt * 8 + g];
                bf[1] = Bs[buf][(ks + t + 4) * BS_STR + wn + nt * 8 + g];
                mma_tf32(acc[0][nt], af[0], bf);
                mma_tf32(acc[1][nt], af[1], bf);
            }
        }
        int nb = buf ^ 1;
        unsigned* d = &As[nb][arow * AS_STR + acolg];
        d[0] = f2tf32(pa0.x); d[1] = f2tf32(pa0.y); d[2] = f2tf32(pa0.z); d[3] = f2tf32(pa0.w);
        d[4] = f2tf32(pa1.x); d[5] = f2tf32(pa1.y); d[6] = f2tf32(pa1.z); d[7] = f2tf32(pa1.w);
        unsigned* e = &Bs[nb][brow * BS_STR + bcol];
        e[0] = f2tf32(pb0.x); e[1] = f2tf32(pb0.y); e[2] = f2tf32(pb0.z); e[3] = f2tf32(pb0.w);
        e[4] = f2tf32(pb1.x); e[5] = f2tf32(pb1.y); e[6] = f2tf32(pb1.z); e[7] = f2tf32(pb1.w);
        __syncthreads();
        buf = nb;
    }
#pragma unroll
    for (int ks = 0; ks < 16; ks += 8) {
        unsigned af[2][4];
#pragma unroll
        for (int mt = 0; mt < 2; mt++) {
            int mb = wm + mt * 16;
            af[mt][0] = As[buf][(mb + g) * AS_STR + ks + t];
            af[mt][1] = As[buf][(mb + g + 8) * AS_STR + ks + t];
            af[mt][2] = As[buf][(mb + g) * AS_STR + ks + t + 4];
            af[mt][3] = As[buf][(mb + g + 8) * AS_STR + ks + t + 4];
        }
#pragma unroll
        for (int nt = 0; nt < 8; nt++) {
            unsigned bf[2];
            bf[0] = Bs[buf][(ks + t) * BS_STR + wn + nt * 8 + g];
            bf[1] = Bs[buf][(ks + t + 4) * BS_STR + wn + nt * 8 + g];
            mma_tf32(acc[0][nt], af[0], bf);
            mma_tf32(acc[1][nt], af[1], bf);
        }
    }

#pragma unroll
    for (int nt = 0; nt < 8; nt++) {
        int cb = n0 + wn + nt * 8 + 2 * t;
        float b0 = __ldg(&bias[cb]), b1 = __ldg(&bias[cb + 1]);
#pragma unroll
        for (int mt = 0; mt < 2; mt++) {
            int r = m0 + wm + mt * 16 + g;
            float2 lo = make_float2(acc[mt][nt][0] + b0, acc[mt][nt][1] + b1);
            float2 hi = make_float2(acc[mt][nt][2] + b0, acc[mt][nt][3] + b1);
            if (relu) {
                lo.x = fmaxf(lo.x, 0.f); lo.y = fmaxf(lo.y, 0.f);
                hi.x = fmaxf(hi.x, 0.f); hi.y = fmaxf(hi.y, 0.f);
            }
            *(float2*)&C[(size_t)r * N + cb] = lo;
            *(float2*)&C[(size_t)(r + 8) * N + cb] = hi;
        }
    }
}

// ---------------- FMA SGEMM 128x128x16 (validated; used for MLP) ----------------
__global__ __launch_bounds__(256)
void gemm128_kernel(const float* __restrict__ A, const float* __restrict__ B,
                    const float* __restrict__ bias, float* __restrict__ C,
                    int M, int N, int K, int relu) {
    __shared__ float As[2][16][128];
    __shared__ float Bs[2][16][132];
    int tid = threadIdx.x;
    int m0 = blockIdx.y * 128, n0 = blockIdx.x * 128;
    int tx = tid & 15, ty = tid >> 4;
    int arow = tid >> 1, acolg = (tid & 1) << 3;
    int brow = tid >> 5, bcol = (tid & 31) << 2;
    const float* Aptr = A + (size_t)(m0 + arow) * K;

    {
        float4 a0 = *(const float4*)&Aptr[acolg];
        float4 a1 = *(const float4*)&Aptr[acolg + 4];
        As[0][acolg + 0][arow] = a0.x; As[0][acolg + 1][arow] = a0.y;
        As[0][acolg + 2][arow] = a0.z; As[0][acolg + 3][arow] = a0.w;
        As[0][acolg + 4][arow] = a1.x; As[0][acolg + 5][arow] = a1.y;
        As[0][acolg + 6][arow] = a1.z; As[0][acolg + 7][arow] = a1.w;
        *(float4*)&Bs[0][brow][bcol]     = *(const float4*)&B[(size_t)brow * N + n0 + bcol];
        *(float4*)&Bs[0][brow + 8][bcol] = *(const float4*)&B[(size_t)(brow + 8) * N + n0 + bcol];
    }
    __syncthreads();

    float acc[8][8] = {};
    int buf = 0;
    for (int k0 = 16; k0 < K; k0 += 16) {
        float4 na0 = *(const float4*)&Aptr[k0 + acolg];
        float4 na1 = *(const float4*)&Aptr[k0 + acolg + 4];
        float4 nb0 = *(const float4*)&B[(size_t)(k0 + brow) * N + n0 + bcol];
        float4 nb1 = *(const float4*)&B[(size_t)(k0 + brow + 8) * N + n0 + bcol];
#pragma unroll
        for (int kk = 0; kk < 16; kk++) {
            float a[8], b[8];
            *(float4*)(a)     = *(const float4*)&As[buf][kk][ty * 8];
            *(float4*)(a + 4) = *(const float4*)&As[buf][kk][ty * 8 + 4];
            *(float4*)(b)     = *(const float4*)&Bs[buf][kk][tx * 8];
            *(float4*)(b + 4) = *(const float4*)&Bs[buf][kk][tx * 8 + 4];
#pragma unroll
            for (int i2 = 0; i2 < 8; i2++)
#pragma unroll
                for (int j2 = 0; j2 < 8; j2++)
                    acc[i2][j2] += a[i2] * b[j2];
        }
        int nb = buf ^ 1;
        As[nb][acolg + 0][arow] = na0.x; As[nb][acolg + 1][arow] = na0.y;
        As[nb][acolg + 2][arow] = na0.z; As[nb][acolg + 3][arow] = na0.w;
        As[nb][acolg + 4][arow] = na1.x; As[nb][acolg + 5][arow] = na1.y;
        As[nb][acolg + 6][arow] = na1.z; As[nb][acolg + 7][arow] = na1.w;
        *(float4*)&Bs[nb][brow][bcol]     = nb0;
        *(float4*)&Bs[nb][brow + 8][bcol] = nb1;
        __syncthreads();
        buf = nb;
    }
#pragma unroll
    for (int kk = 0; kk < 16; kk++) {
        float a[8], b[8];
        *(float4*)(a)     = *(const float4*)&As[buf][kk][ty * 8];
        *(float4*)(a + 4) = *(const float4*)&As[buf][kk][ty * 8 + 4];
        *(float4*)(b)     = *(const float4*)&Bs[buf][kk][tx * 8];
        *(float4*)(b + 4) = *(const float4*)&Bs[buf][kk][tx * 8 + 4];
#pragma unroll
        for (int i2 = 0; i2 < 8; i2++)
#pragma unroll
            for (int j2 = 0; j2 < 8; j2++)
                acc[i2][j2] += a[i2] * b[j2];
    }

    float4 bi0 = *(const float4*)&bias[n0 + tx * 8];
    float4 bi1 = *(const float4*)&bias[n0 + tx * 8 + 4];
#pragma unroll
    for (int r = 0; r < 8; r++) {
        float* crow = C + (size_t)(m0 + ty * 8 + r) * N + n0 + tx * 8;
        float4 o0 = make_float4(acc[r][0] + bi0.x, acc[r][1] + bi0.y,
                                acc[r][2] + bi0.z, acc[r][3] + bi0.w);
        float4 o1 = make_float4(acc[r][4] + bi1.x, acc[r][5] + bi1.y,
                                acc[r][6] + bi1.z, acc[r][7] + bi1.w);
        if (relu) {
            o0.x = fmaxf(o0.x, 0.f); o0.y = fmaxf(o0.y, 0.f);
            o0.z = fmaxf(o0.z, 0.f); o0.w = fmaxf(o0.w, 0.f);
            o1.x = fmaxf(o1.x, 0.f); o1.y = fmaxf(o1.y, 0.f);
            o1.z = fmaxf(o1.z, 0.f); o1.w = fmaxf(o1.w, 0.f);
        }
        *(float4*)crow = o0;
        *(float4*)(crow + 4) = o1;
    }
}

// ---------------- FMA out-proj + residual + LayerNorm (validated R6-R12) ----------------
__global__ __launch_bounds__(256)
void gemm_wo_ln_kernel(const float* __restrict__ A, const float* __restrict__ B,
                       const float* __restrict__ bias, const float* __restrict__ xres,
                       const float* __restrict__ g, const float* __restrict__ bb,
                       float* __restrict__ out) {
    __shared__ float As[2][16][128];
    __shared__ float Bs[2][16][132];
    int tid = threadIdx.x;
    int m0 = blockIdx.x * 128;
    int tx = tid & 15, ty = tid >> 4;
    int arow = tid >> 1, acolg = (tid & 1) << 3;
    int brow = tid >> 5, bcol = (tid & 31) << 2;
    const float* Aptr = A + (size_t)(m0 + arow) * 128;

    {
        float4 a0 = *(const float4*)&Aptr[acolg];
        float4 a1 = *(const float4*)&Aptr[acolg + 4];
        As[0][acolg + 0][arow] = a0.x; As[0][acolg + 1][arow] = a0.y;
        As[0][acolg + 2][arow] = a0.z; As[0][acolg + 3][arow] = a0.w;
        As[0][acolg + 4][arow] = a1.x; As[0][acolg + 5][arow] = a1.y;
        As[0][acolg + 6][arow] = a1.z; As[0][acolg + 7][arow] = a1.w;
        *(float4*)&Bs[0][brow][bcol]     = *(const float4*)&B[(size_t)brow * 128 + bcol];
        *(float4*)&Bs[0][brow + 8][bcol] = *(const float4*)&B[(size_t)(brow + 8) * 128 + bcol];
    }
    __syncthreads();

    float acc[8][8] = {};
    int buf = 0;
    for (int k0 = 16; k0 < 128; k0 += 16) {
        float4 na0 = *(const float4*)&Aptr[k0 + acolg];
        float4 na1 = *(const float4*)&Aptr[k0 + acolg + 4];
        float4 nb0 = *(const float4*)&B[(size_t)(k0 + brow) * 128 + bcol];
        float4 nb1 = *(const float4*)&B[(size_t)(k0 + brow + 8) * 128 + bcol];
#pragma unroll
        for (int kk = 0; kk < 16; kk++) {
            float a[8], b[8];
            *(float4*)(a)     = *(const float4*)&As[buf][kk][ty * 8];
            *(float4*)(a + 4) = *(const float4*)&As[buf][kk][ty * 8 + 4];
            *(float4*)(b)     = *(const float4*)&Bs[buf][kk][tx * 8];
            *(float4*)(b + 4) = *(const float4*)&Bs[buf][kk][tx * 8 + 4];
#pragma unroll
            for (int i2 = 0; i2 < 8; i2++)
#pragma unroll
                for (int j2 = 0; j2 < 8; j2++)
                    acc[i2][j2] += a[i2] * b[j2];
        }
        int nb = buf ^ 1;
        As[nb][acolg + 0][arow] = na0.x; As[nb][acolg + 1][arow] = na0.y;
        As[nb][acolg + 2][arow] = na0.z; As[nb][acolg + 3][arow] = na0.w;
        As[nb][acolg + 4][arow] = na1.x; As[nb][acolg + 5][arow] = na1.y;
        As[nb][acolg + 6][arow] = na1.z; As[nb][acolg + 7][arow] = na1.w;
        *(float4*)&Bs[nb][brow][bcol]     = nb0;
        *(float4*)&Bs[nb][brow + 8][bcol] = nb1;
        __syncthreads();
        buf = nb;
    }
#pragma unroll
    for (int kk = 0; kk < 16; kk++) {
        float a[8], b[8];
        *(float4*)(a)     = *(const float4*)&As[buf][kk][ty * 8];
        *(float4*)(a + 4) = *(const float4*)&As[buf][kk][ty * 8 + 4];
        *(float4*)(b)     = *(const float4*)&Bs[buf][kk][tx * 8];
        *(float4*)(b + 4) = *(const float4*)&Bs[buf][kk][tx * 8 + 4];
#pragma unroll
        for (int i2 = 0; i2 < 8; i2++)
#pragma unroll
            for (int j2 = 0; j2 < 8; j2++)
                acc[i2][j2] += a[i2] * b[j2];
    }

    float4 bi0 = *(const float4*)&bias[tx * 8];
    float4 bi1 = *(const float4*)&bias[tx * 8 + 4];
    float4 g0  = *(const float4*)&g[tx * 8];
    float4 g1  = *(const float4*)&g[tx * 8 + 4];
    float4 be0 = *(const float4*)&bb[tx * 8];
    float4 be1 = *(const float4*)&bb[tx * 8 + 4];
#pragma unroll
    for (int r = 0; r < 8; r++) {
        int row = m0 + ty * 8 + r;
        const float* xr = xres + (size_t)row * 128 + tx * 8;
        float4 x0 = *(const float4*)xr;
        float4 x1 = *(const float4*)(xr + 4);
        float v[8];
        v[0] = acc[r][0] + bi0.x + x0.x; v[1] = acc[r][1] + bi0.y + x0.y;
        v[2] = acc[r][2] + bi0.z + x0.z; v[3] = acc[r][3] + bi0.w + x0.w;
        v[4] = acc[r][4] + bi1.x + x1.x; v[5] = acc[r][5] + bi1.y + x1.y;
        v[6] = acc[r][6] + bi1.z + x1.z; v[7] = acc[r][7] + bi1.w + x1.w;
        float s = 0.f;
#pragma unroll
        for (int q = 0; q < 8; q++) s += v[q];
        s = half16_sum(s);
        float mean = s * (1.0f / 128.0f);
        float d2 = 0.f;
#pragma unroll
        for (int q = 0; q < 8; q++) { float d = v[q] - mean; d2 += d * d; }
        d2 = half16_sum(d2);
        float inv = rsqrtf(d2 * (1.0f / 128.0f) + 1e-5f);
        float* orow = out + (size_t)row * 128 + tx * 8;
        float4 o0, o1;
        o0.x = (v[0] - mean) * inv * g0.x + be0.x;
        o0.y = (v[1] - mean) * inv * g0.y + be0.y;
        o0.z = (v[2] - mean) * inv * g0.z + be0.z;
        o0.w = (v[3] - mean) * inv * g0.w + be0.w;
        o1.x = (v[4] - mean) * inv * g1.x + be1.x;
        o1.y = (v[5] - mean) * inv * g1.y + be1.y;
        o1.z = (v[6] - mean) * inv * g1.z + be1.z;
        o1.w = (v[7] - mean) * inv * g1.w + be1.w;
        *(float4*)orow = o0;
        *(float4*)(orow + 4) = o1;
    }
}

// ---------------- tensor-core attention: block per (jt, h, i), 256 threads ----------------
// QK^T: D[64j x 256k], warp = 16j x 128k (w&3 = j-tile, w>>2 = k-half). AV: warp = 16j x 16d.
// smem (u32 words): Qs[64][36] | Ks[32][264] | Vs[256][40] | S[64][264] | redM[2][64] | redS[2][64]
#define ATQ_STR 36
#define ATK_STR 264
#define ATV_STR 40
#define ATS_STR 264
#define ATT_QS 0
#define ATT_KS (64 * ATQ_STR)
#define ATT_VS (ATT_KS + 32 * ATK_STR)
#define ATT_S  (ATT_VS + 256 * ATV_STR)
#define ATT_RM (ATT_S + 64 * ATS_STR)
#define ATT_RS (ATT_RM + 128)
#define ATT_WORDS (ATT_RS + 128)
#define ATT_SMEM_BYTES (ATT_WORDS * 4)

__global__ __launch_bounds__(256)
void attn_tc_kernel(const float* __restrict__ qkv, const float* __restrict__ biasmat,
                    float* __restrict__ out) {
    extern __shared__ unsigned ush[];
    unsigned* Qs = ush + ATT_QS;      // [j][d] tf32
    unsigned* Ks = ush + ATT_KS;      // [d][k] tf32
    unsigned* Vs = ush + ATT_VS;      // [k][d] tf32
    unsigned* S  = ush + ATT_S;       // [j][k] exp-weights tf32
    float* redM = (float*)(ush + ATT_RM);
    float* redS = (float*)(ush + ATT_RS);
    int jt = blockIdx.x, h = blockIdx.y, i = blockIdx.z;
    int tid = threadIdx.x, lane = tid & 31, w = tid >> 5;
    int g = lane >> 2, t = lane & 3;
    int wm = (w & 3) * 16;            // j-tile base (local)
    int ch = w >> 2;                  // k column half
    int wn2 = ch * 128;
    const float* base = qkv + (size_t)i * NSEQ * 384;

    for (int idx = tid; idx < 64 * 32; idx += 256) {
        int j = idx >> 5, d = idx & 31;
        Qs[j * ATQ_STR + d] = f2tf32(base[(size_t)(jt * 64 + j) * 384 + h * 32 + d]);
    }
    for (int idx = tid; idx < 256 * 32; idx += 256) {
        int k = idx >> 5, d = idx & 31;
        Ks[d * ATK_STR + k] = f2tf32(base[(size_t)k * 384 + 128 + h * 32 + d]);
        Vs[k * ATV_STR + d] = f2tf32(base[(size_t)k * 384 + 256 + h * 32 + d]);
    }
    __syncthreads();

    const float scale = 0.17677669529663687f;  // 1/sqrt(32)

    // ---- QK^T via mma: acc[nt][4], nt over 16 n-tiles of 8 ----
    float acc[16][4];
#pragma unroll
    for (int nt = 0; nt < 16; nt++)
#pragma unroll
        for (int q = 0; q < 4; q++) acc[nt][q] = 0.f;

#pragma unroll
    for (int ks = 0; ks < 32; ks += 8) {
        unsigned af[4];
        af[0] = Qs[(wm + g) * ATQ_STR + ks + t];
        af[1] = Qs[(wm + g + 8) * ATQ_STR + ks + t];
        af[2] = Qs[(wm + g) * ATQ_STR + ks + t + 4];
        af[3] = Qs[(wm + g + 8) * ATQ_STR + ks + t + 4];
#pragma unroll
        for (int nt = 0; nt < 16; nt++) {
            unsigned bf[2];
            bf[0] = Ks[(ks + t) * ATK_STR + wn2 + nt * 8 + g];
            bf[1] = Ks[(ks + t + 4) * ATK_STR + wn2 + nt * 8 + g];
            mma_tf32(acc[nt], af, bf);
        }
    }

    // ---- scale + bias, row max over own half ----
    int row_lo = jt * 64 + wm + g, row_hi = row_lo + 8;
    float mx_lo = -1e30f, mx_hi = -1e30f;
#pragma unroll
    for (int nt = 0; nt < 16; nt++) {
        int cb = wn2 + nt * 8 + 2 * t;
        float2 bl = __ldg((const float2*)(biasmat + (size_t)row_lo * 256 + cb));
        float2 bh = __ldg((const float2*)(biasmat + (size_t)row_hi * 256 + cb));
        acc[nt][0] = fmaf(acc[nt][0], scale, bl.x);
        acc[nt][1] = fmaf(acc[nt][1], scale, bl.y);
        acc[nt][2] = fmaf(acc[nt][2], scale, bh.x);
        acc[nt][3] = fmaf(acc[nt][3], scale, bh.y);
        mx_lo = fmaxf(mx_lo, fmaxf(acc[nt][0], acc[nt][1]));
        mx_hi = fmaxf(mx_hi, fmaxf(acc[nt][2], acc[nt][3]));
    }
    mx_lo = fmaxf(mx_lo, __shfl_xor_sync(0xffffffffu, mx_lo, 1));
    mx_lo = fmaxf(mx_lo, __shfl_xor_sync(0xffffffffu, mx_lo, 2));
    mx_hi = fmaxf(mx_hi, __shfl_xor_sync(0xffffffffu, mx_hi, 1));
    mx_hi = fmaxf(mx_hi, __shfl_xor_sync(0xffffffffu, mx_hi, 2));
    if (t == 0) {
        redM[ch * 64 + wm + g] = mx_lo;
        redM[ch * 64 + wm + g + 8] = mx_hi;
    }
    __syncthreads();
    mx_lo = fmaxf(mx_lo, redM[(1 - ch) * 64 + wm + g]);
    mx_hi = fmaxf(mx_hi, redM[(1 - ch) * 64 + wm + g + 8]);

    // ---- exp, partial sums, write tf32 S ----
    float sum_lo = 0.f, sum_hi = 0.f;
#pragma unroll
    for (int nt = 0; nt < 16; nt++) {
        float e0 = __expf(acc[nt][0] - mx_lo);
        float e1 = __expf(acc[nt][1] - mx_lo);
        float e2 = __expf(acc[nt][2] - mx_hi);
        float e3 = __expf(acc[nt][3] - mx_hi);
        sum_lo += e0 + e1;
        sum_hi += e2 + e3;
        int cb = wn2 + nt * 8 + 2 * t;
        uint2 slo = make_uint2(f2tf32(e0), f2tf32(e1));
        uint2 shi = make_uint2(f2tf32(e2), f2tf32(e3));
        *(uint2*)&S[(wm + g) * ATS_STR + cb] = slo;
        *(uint2*)&S[(wm + g + 8) * ATS_STR + cb] = shi;
    }
    sum_lo += __shfl_xor_sync(0xffffffffu, sum_lo, 1);
    sum_lo += __shfl_xor_sync(0xffffffffu, sum_lo, 2);
    sum_hi += __shfl_xor_sync(0xffffffffu, sum_hi, 1);
    sum_hi += __shfl_xor_sync(0xffffffffu, sum_hi, 2);
    if (t == 0) {
        redS[ch * 64 + wm + g] = sum_lo;
        redS[ch * 64 + wm + g + 8] = sum_hi;
    }
    __syncthreads();   // also publishes S to all warps
    float inv_lo = 1.0f / (sum_lo + redS[(1 - ch) * 64 + wm + g]);
    float inv_hi = 1.0f / (sum_hi + redS[(1 - ch) * 64 + wm + g + 8]);

    // ---- AV via mma: D2[64j x 32d], warp = 16j x 16d ----
    int wn_av = ch * 16;
    float acc2[2][4] = {};
    for (int kb = 0; kb < 256; kb += 8) {
        unsigned af[4];
        af[0] = S[(wm + g) * ATS_STR + kb + t];
        af[1] = S[(wm + g + 8) * ATS_STR + kb + t];
        af[2] = S[(wm + g) * ATS_STR + kb + t + 4];
        af[3] = S[(wm + g + 8) * ATS_STR + kb + t + 4];
#pragma unroll
        for (int nt = 0; nt < 2; nt++) {
            unsigned bf[2];
            bf[0] = Vs[(kb + t) * ATV_STR + wn_av + nt * 8 + g];
            bf[1] = Vs[(kb + t + 4) * ATV_STR + wn_av + nt * 8 + g];
            mma_tf32(acc2[nt], af, bf);
        }
    }

#pragma unroll
    for (int nt = 0; nt < 2; nt++) {
        int col = wn_av + nt * 8 + 2 * t;
        float2 olo = make_float2(acc2[nt][0] * inv_lo, acc2[nt][1] * inv_lo);
        float2 ohi = make_float2(acc2[nt][2] * inv_hi, acc2[nt][3] * inv_hi);
        *(float2*)&out[((size_t)i * NSEQ + row_lo) * CDIM + h * 32 + col] = olo;
        *(float2*)&out[((size_t)i * NSEQ + row_hi) * CDIM + h * 32 + col] = ohi;
    }
}

// ---------------- launch ----------------
extern "C" void kernel_launch(void* const* d_in, const int* in_sizes, int n_in,
                              void* d_out, int out_size) {
    const float* pair      = (const float*)d_in[0];
    const float* single    = (const float*)d_in[1];
    const unsigned char* mask = (const unsigned char*)d_in[2];
    const float* dist      = (const float*)d_in[3];
    const float* row_Wqkv  = (const float*)d_in[4];
    const float* row_bqkv  = (const float*)d_in[5];
    const float* row_Wo    = (const float*)d_in[6];
    const float* row_bo    = (const float*)d_in[7];
    const float* row_dsc   = (const float*)d_in[8];
    const float* col_Wqkv  = (const float*)d_in[9];
    const float* col_bqkv  = (const float*)d_in[10];
    const float* col_Wo    = (const float*)d_in[11];
    const float* col_bo    = (const float*)d_in[12];
    const float* col_dsc   = (const float*)d_in[13];
    const float* pnr_g     = (const float*)d_in[14];
    const float* pnr_b     = (const float*)d_in[15];
    const float* pnc_g     = (const float*)d_in[16];
    const float* pnc_b     = (const float*)d_in[17];
    const float* sn_g      = (const float*)d_in[18];
    const float* sn_b      = (const float*)d_in[19];
    const float* W1        = (const float*)d_in[20];
    const float* b1        = (const float*)d_in[21];
    const float* W2        = (const float*)d_in[22];
    const float* b2        = (const float*)d_in[23];

    float* pr = (float*)d_out;                               // [256,256,128]
    float* sr = pr + (size_t)NROWS * CDIM;                   // [256,128]

    float *qkv_p, *attn_p, *h1_p, *h2_p, *brow_p, *bcol_p;
    cudaGetSymbolAddress((void**)&qkv_p, g_qkv);
    cudaGetSymbolAddress((void**)&attn_p, g_attn);
    cudaGetSymbolAddress((void**)&h1_p, g_h1);
    cudaGetSymbolAddress((void**)&h2_p, g_h2);
    cudaGetSymbolAddress((void**)&brow_p, g_bias_row);
    cudaGetSymbolAddress((void**)&bcol_p, g_bias_col);

    cudaFuncSetAttribute(attn_tc_kernel, cudaFuncAttributeMaxDynamicSharedMemorySize,
                         ATT_SMEM_BYTES);

    // mask detection + fused bias tables
    maskbias_kernel<<<1, 1024>>>(mask, dist, row_dsc, col_dsc);

    // ---- stage 1: pr = LN(pair + tri_update_out(pair, single)) ----
    rowsum_kernel<<<NSEQ, CDIM>>>(pair);
    trimix_ln_kernel<<<NROWS / 8, 256>>>(pr, pair, single, pnr_g, pnr_b, 0);

    // ---- stage 2: pr = LN(pr + row_attn(pr)) ----
    gemm_tf32_kernel<<<dim3(3, 512), 256>>>(pr, row_Wqkv, row_bqkv, qkv_p, NROWS, 384, 128, 0);
    attn_tc_kernel<<<dim3(4, NHEAD, NSEQ), 256, ATT_SMEM_BYTES>>>(qkv_p, brow_p, attn_p);
    gemm_wo_ln_kernel<<<512, 256>>>(attn_p, row_Wo, row_bo, pr, pnr_g, pnr_b, pr);

    // ---- stage 3: pr = LN(pr + tri_update_in(pr, single)) ----
    colsum_kernel<<<NSEQ, CDIM>>>(pr);
    trimix_ln_kernel<<<NROWS / 8, 256>>>(pr, pr, single, pnc_g, pnc_b, 1);

    // ---- stage 4: pr = LN(pr + col_attn(pr)) ----
    gemm_tf32_kernel<<<dim3(3, 512), 256>>>(pr, col_Wqkv, col_bqkv, qkv_p, NROWS, 384, 128, 0);
    attn_tc_kernel<<<dim3(4, NHEAD, NSEQ), 256, ATT_SMEM_BYTES>>>(qkv_p, bcol_p, attn_p);
    gemm_wo_ln_kernel<<<512, 256>>>(attn_p, col_Wo, col_bo, pr, pnc_g, pnc_b, pr);

    // ---- single-rep MLP + LN ----
    gemm128_kernel<<<dim3(2, 2), 256>>>(single, W1, b1, h1_p, NSEQ, 256, 128, 1);
    gemm128_kernel<<<dim3(1, 2), 256>>>(h1_p, W2, b2, h2_p, NSEQ, 128, 256, 1);
    residual_ln_kernel<<<NSEQ / 8, 256>>>(sr, single, h2_p, sn_g, sn_b, NSEQ);
}